// round 14
// baseline (speedup 1.0000x reference)
#include <cuda_runtime.h>

// Problem constants (fixed by the reference).
#define TT   1024
#define BB   16384
#define CH   32          // steps per chunk
#define SQ   5           // log2(CH) squarings for Wx^CH
#define NCH  (TT / CH)   // 32 chunks
#define QB   (BB / 4)    // thread columns (4 adjacent elements per thread)

typedef unsigned long long u64;

static_assert((1 << SQ) == CH, "SQ must be log2(CH)");
static_assert(TT % CH == 0, "");

// Scratch.
__device__ float g_part[NCH * 6 * BB];   // zero-state per-chunk db partials
__device__ float g_ckpt[NCH * 6 * BB];   // true db at chunk entry
__device__ float g_m[CH * 6];            // m_s = Wx^s * Wu
__device__ float g_MC[36];               // Wx^CH

// Duplicated-pair weight table, staged by kP then copied to constant bank.
// Layout (u64 units):
//   rows i=0..5 at i*8: [Wx i0..i5 (pairs), Wu i (pair), pad]   (cw[7] = b2 pair)
//   rows j=0..19 at 48+j*16: [W1 j0..j11 (pairs), b1 j, W2 j, pad, pad]
#define CW_N 368
#define SW_ROWJ(j) (48 + (j) * 16)
__device__ u64 g_wdup[CW_N];
__constant__ __align__(16) u64 cw[CW_N];

// ---- f32x2 helpers (sm_100+ packed fp32 pipe) ----
__device__ __forceinline__ u64 pack2(float lo, float hi) {
    u64 r; asm("mov.b64 %0,{%1,%2};" : "=l"(r) : "f"(lo), "f"(hi)); return r;
}
__device__ __forceinline__ void unpack2(u64 v, float& lo, float& hi) {
    asm("mov.b64 {%0,%1},%2;" : "=f"(lo), "=f"(hi) : "l"(v));
}
__device__ __forceinline__ u64 fma2(u64 a, u64 b, u64 c) {
    u64 d; asm("fma.rn.f32x2 %0,%1,%2,%3;" : "=l"(d) : "l"(a), "l"(b), "l"(c)); return d;
}
__device__ __forceinline__ u64 mul2(u64 a, u64 b) {
    u64 d; asm("mul.rn.f32x2 %0,%1,%2;" : "=l"(d) : "l"(a), "l"(b)); return d;
}
__device__ __forceinline__ float tanh_(float x) {
    float y; asm("tanh.approx.f32 %0,%1;" : "=f"(y) : "f"(x)); return y;
}

// ============================================================
// Kernel P: precompute m_s = Wx^s Wu, Wx^CH, and the duplicated
// weight-pair table g_wdup. One block of 64 threads.
// ============================================================
__global__ void __launch_bounds__(64) kP(const float* __restrict__ Wx,
                                         const float* __restrict__ Wu,
                                         const float* __restrict__ W1,
                                         const float* __restrict__ b1,
                                         const float* __restrict__ W2,
                                         const float* __restrict__ b2) {
    __shared__ float sM[36], sm[6], sP[36], st[36];
    int t = threadIdx.x;
    if (t < 36) sM[t] = Wx[t];
    if (t < 6)  sm[t] = Wu[t];
    __syncthreads();

    for (int s = 0; s < CH; s++) {
        if (t < 6) g_m[s * 6 + t] = sm[t];
        __syncthreads();
        float nv = 0.f;
        if (t < 6) {
#pragma unroll
            for (int k = 0; k < 6; k++) nv = fmaf(sM[t * 6 + k], sm[k], nv);
        }
        __syncthreads();
        if (t < 6) sm[t] = nv;
        __syncthreads();
    }

    if (t < 36) sP[t] = sM[t];
    __syncthreads();
    for (int p = 0; p < SQ; p++) {
        if (t < 36) {
            int i = t / 6, j = t % 6;
            float a = 0.f;
#pragma unroll
            for (int k = 0; k < 6; k++) a = fmaf(sP[i * 6 + k], sP[k * 6 + j], a);
            st[t] = a;
        }
        __syncthreads();
        if (t < 36) sP[t] = st[t];
        __syncthreads();
    }
    if (t < 36) g_MC[t] = sP[t];

    // ---- duplicated-pair weight table ----
    if (t < 36) {
        float w = Wx[t];
        g_wdup[(t / 6) * 8 + (t % 6)] = pack2(w, w);
    } else if (t < 42) {
        int i = t - 36;
        float w = Wu[i];
        g_wdup[i * 8 + 6] = pack2(w, w);
        if (i > 0) g_wdup[i * 8 + 7] = 0ull;
    } else if (t < 62) {
        int j = t - 42;
        for (int i = 0; i < 12; i++) {
            float w = W1[j * 12 + i];
            g_wdup[SW_ROWJ(j) + i] = pack2(w, w);
        }
        float bj = b1[j];
        g_wdup[SW_ROWJ(j) + 12] = pack2(bj, bj);
        float w2j = W2[j];
        g_wdup[SW_ROWJ(j) + 13] = pack2(w2j, w2j);
        g_wdup[SW_ROWJ(j) + 14] = 0ull;
        g_wdup[SW_ROWJ(j) + 15] = 0ull;
    } else if (t == 62) {
        float bv = b2[0];
        g_wdup[7] = pack2(bv, bv);   // b2 pair in row-0 pad slot
    }
}

// ============================================================
// Kernel A: per-chunk zero-state db partials via convolution.
// Vectorized: 4 adjacent batch elements per thread (float4 I/O).
// grid ((BB/4)/256, NCH), block 256.
// ============================================================
__global__ void __launch_bounds__(256) kA(const float* __restrict__ targets) {
    __shared__ float sm[CH * 6];
    int tid = threadIdx.x;
    for (int i = tid; i < CH * 6; i += 256) sm[i] = g_m[i];
    __syncthreads();

    int q  = blockIdx.x * 256 + tid;   // 0..BB/4-1
    int e0 = q * 4;
    int c  = blockIdx.y;
    int t0 = c * CH;

    float4 acc[6];
#pragma unroll
    for (int i = 0; i < 6; i++) acc[i] = make_float4(0.f, 0.f, 0.f, 0.f);

#pragma unroll 4
    for (int s = 0; s < CH; s++) {
        int t = t0 + s;
        float4 u = make_float4(0.f, 0.f, 0.f, 0.f);
        if (t > 0)
            u = *(const float4*)(targets + (size_t)(t - 1) * BB + e0);
        const float* mm = &sm[(CH - 1 - s) * 6];
#pragma unroll
        for (int i = 0; i < 6; i++) {
            float m = mm[i];
            acc[i].x = fmaf(m, u.x, acc[i].x);
            acc[i].y = fmaf(m, u.y, acc[i].y);
            acc[i].z = fmaf(m, u.z, acc[i].z);
            acc[i].w = fmaf(m, u.w, acc[i].w);
        }
    }
#pragma unroll
    for (int i = 0; i < 6; i++)
        *(float4*)(g_part + ((size_t)c * 6 + i) * BB + e0) = acc[i];
}

// ============================================================
// Kernel B: scan across chunks: db_in(c+1) = Wx^CH * db_in(c) + partial(c).
// Vectorized: 4 adjacent batch elements per thread (float4 I/O).
// grid ((BB/4)/256), block 256.
// ============================================================
__global__ void __launch_bounds__(256) kB() {
    __shared__ float sM[36];
    int tid = threadIdx.x;
    if (tid < 36) sM[tid] = g_MC[tid];
    __syncthreads();

    int q  = blockIdx.x * 256 + tid;
    int e0 = q * 4;

    float4 v[6];
#pragma unroll
    for (int i = 0; i < 6; i++) v[i] = make_float4(0.f, 0.f, 0.f, 0.f);

#pragma unroll 1
    for (int c = 0; c < NCH; c++) {
#pragma unroll
        for (int i = 0; i < 6; i++)
            *(float4*)(g_ckpt + ((size_t)c * 6 + i) * BB + e0) = v[i];
        float4 pr[6];
#pragma unroll
        for (int i = 0; i < 6; i++)
            pr[i] = *(const float4*)(g_part + ((size_t)c * 6 + i) * BB + e0);
        float4 nv[6];
#pragma unroll
        for (int i = 0; i < 6; i++) {
            float4 a = pr[i];
#pragma unroll
            for (int j = 0; j < 6; j++) {
                float m = sM[i * 6 + j];
                a.x = fmaf(m, v[j].x, a.x);
                a.y = fmaf(m, v[j].y, a.y);
                a.z = fmaf(m, v[j].z, a.z);
                a.w = fmaf(m, v[j].w, a.w);
            }
            nv[i] = a;
        }
#pragma unroll
        for (int i = 0; i < 6; i++) v[i] = nv[i];
    }
}

// ============================================================
// Kernel C: fused MLP. Weights from the constant bank (warp-uniform
// LDCU -> UR operands). FOUR ADJACENT batch elements per thread
// (4p..4p+3) as two f32x2 pairs; all gmem traffic is LDG.128/STG.128.
// R14 experiment: (128,3) — cap 170 regs so the ~140-reg live set fits
// WITHOUT spilling (R12/R13 at (128,4) spilled: L1 31%). Inner loop
// byte-identical to R13.
// ============================================================
__global__ void __launch_bounds__(128, 3) kC(const float* __restrict__ inputs,
                                             const float* __restrict__ targets,
                                             float* __restrict__ out) {
    const int tid = threadIdx.x;
    const int c   = blockIdx.y;
    const int p   = blockIdx.x * 128 + tid;   // 0..QB-1
    const int e0  = p * 4;                    // first of 4 adjacent elements

    // nA/nB: [0..5] = db (live state), [6..11] = packed x of current step
    u64 nA[12], nB[12];
    {
        const char* ck = (const char*)g_ckpt + ((size_t)c * 6 * BB + e0) * 4;
#pragma unroll
        for (int i = 0; i < 6; i++) {
            float4 v = *(const float4*)(ck + (size_t)i * BB * 4);
            nA[i] = pack2(v.x, v.y);
            nB[i] = pack2(v.z, v.w);
        }
    }

    const char* xp = (const char*)inputs  + ((size_t)c * CH * BB + e0) * 24;
    const char* tp = (const char*)targets + ((size_t)(c * CH - 1) * BB + e0) * 4;
    char*       op = (char*)out           + ((size_t)c * CH * BB + e0) * 4;

    const float b2v = ((const float*)cw)[14];   // low half of cw[7]

#pragma unroll 1
    for (int s = 0; s < CH; s++) {
        // ---- loads: 4 adjacent elements = 96 contiguous bytes = 6 x LDG.128 ----
        float4 f0 = ((const float4*)xp)[0];
        float4 f1 = ((const float4*)xp)[1];
        float4 f2 = ((const float4*)xp)[2];
        float4 f3 = ((const float4*)xp)[3];
        float4 f4 = ((const float4*)xp)[4];
        float4 f5 = ((const float4*)xp)[5];
        xp += (size_t)BB * 24;

        u64 uA, uB;
        if (c + s > 0) {                  // global step t = c*CH+s > 0
            float4 uv = *(const float4*)tp;
            uA = pack2(uv.x, uv.y);
            uB = pack2(uv.z, uv.w);
        } else {
            uA = 0ull; uB = 0ull;
        }
        tp += (size_t)BB * 4;

        // ---- pack x (frees f0..f5 before recurrence temps are live) ----
        // elem0 = f0.x..f1.y, elem1 = f1.z..f2.w, elem2 = f3.x..f4.y, elem3 = f4.z..f5.w
        nA[6]  = pack2(f0.x, f1.z);   nB[6]  = pack2(f3.x, f4.z);
        nA[7]  = pack2(f0.y, f1.w);   nB[7]  = pack2(f3.y, f4.w);
        nA[8]  = pack2(f0.z, f2.x);   nB[8]  = pack2(f3.z, f5.x);
        nA[9]  = pack2(f0.w, f2.y);   nB[9]  = pack2(f3.w, f5.y);
        nA[10] = pack2(f1.x, f2.z);   nB[10] = pack2(f4.x, f5.z);
        nA[11] = pack2(f1.y, f2.w);   nB[11] = pack2(f4.y, f5.w);

        // ---- db recurrence for both pairs (interleaved chains) ----
        u64 dA[6], dB[6];
#pragma unroll
        for (int i = 0; i < 6; i++) {
            const u64* r = &cw[i * 8];
            u64 a = mul2(r[6], uA);
            u64 b = mul2(r[6], uB);
            a = fma2(r[0], nA[0], a);  b = fma2(r[0], nB[0], b);
            a = fma2(r[1], nA[1], a);  b = fma2(r[1], nB[1], b);
            a = fma2(r[2], nA[2], a);  b = fma2(r[2], nB[2], b);
            a = fma2(r[3], nA[3], a);  b = fma2(r[3], nB[3], b);
            a = fma2(r[4], nA[4], a);  b = fma2(r[4], nB[4], b);
            a = fma2(r[5], nA[5], a);  b = fma2(r[5], nB[5], b);
            dA[i] = a;  dB[i] = b;
        }
#pragma unroll
        for (int i = 0; i < 6; i++) { nA[i] = dA[i]; nB[i] = dB[i]; }

        // ---- MLP: 20 hidden rows, 2 rows x 2 pairs = 4 concurrent chains ----
        float o0 = b2v, o1 = b2v, o2 = b2v, o3 = b2v;
#pragma unroll
        for (int jg = 0; jg < 10; jg++) {
            const int j0 = jg * 2;
            u64 a0 = cw[SW_ROWJ(j0 + 0) + 12], b0 = a0;
            u64 a1 = cw[SW_ROWJ(j0 + 1) + 12], b1 = a1;
#pragma unroll
            for (int k = 0; k < 12; k++) {
                u64 w0 = cw[SW_ROWJ(j0 + 0) + k];
                u64 w1 = cw[SW_ROWJ(j0 + 1) + k];
                a0 = fma2(w0, nA[k], a0);  b0 = fma2(w0, nB[k], b0);
                a1 = fma2(w1, nA[k], a1);  b1 = fma2(w1, nB[k], b1);
            }
            float lo, hi, w2s;
            w2s = ((const float*)cw)[(SW_ROWJ(j0 + 0) + 13) * 2];
            unpack2(a0, lo, hi); o0 = fmaf(w2s, tanh_(lo), o0); o1 = fmaf(w2s, tanh_(hi), o1);
            unpack2(b0, lo, hi); o2 = fmaf(w2s, tanh_(lo), o2); o3 = fmaf(w2s, tanh_(hi), o3);
            w2s = ((const float*)cw)[(SW_ROWJ(j0 + 1) + 13) * 2];
            unpack2(a1, lo, hi); o0 = fmaf(w2s, tanh_(lo), o0); o1 = fmaf(w2s, tanh_(hi), o1);
            unpack2(b1, lo, hi); o2 = fmaf(w2s, tanh_(lo), o2); o3 = fmaf(w2s, tanh_(hi), o3);
        }

        // ---- store: 4 adjacent elements, one STG.128 ----
        float4 ov = make_float4(o0, o1, o2, o3);
        *(float4*)op = ov;
        op += (size_t)BB * 4;
    }
}

// ============================================================
extern "C" void kernel_launch(void* const* d_in, const int* in_sizes, int n_in,
                              void* d_out, int out_size) {
    (void)in_sizes; (void)n_in; (void)out_size;
    const float* inputs  = (const float*)d_in[0];
    const float* targets = (const float*)d_in[1];
    const float* Wx      = (const float*)d_in[2];
    const float* Wu      = (const float*)d_in[3];
    const float* W1      = (const float*)d_in[4];
    const float* b1      = (const float*)d_in[5];
    const float* W2      = (const float*)d_in[6];
    const float* b2      = (const float*)d_in[7];
    float* out = (float*)d_out;

    kP<<<1, 64>>>(Wx, Wu, W1, b1, W2, b2);

    // Stage the duplicated weight table into the constant bank (D2D memcpy node).
    void* wd = nullptr;
    cudaGetSymbolAddress(&wd, g_wdup);
    cudaMemcpyToSymbolAsync(cw, wd, CW_N * sizeof(u64), 0,
                            cudaMemcpyDeviceToDevice, 0);

    dim3 gA((BB / 4) / 256, NCH);
    kA<<<gA, 256>>>(targets);
    kB<<<(BB / 4) / 256, 256>>>();
    dim3 gC(QB / 128, NCH);
    kC<<<gC, 128>>>(inputs, targets, out);
}

// round 16
// speedup vs baseline: 1.2719x; 1.2719x over previous
#include <cuda_runtime.h>

// Problem constants (fixed by the reference).
#define TT   1024
#define BB   16384
#define CH   32          // steps per chunk
#define SQ   5           // log2(CH) squarings for Wx^CH
#define NCH  (TT / CH)   // 32 chunks
#define HB   (BB / 2)    // batch pairs

typedef unsigned long long u64;

static_assert((1 << SQ) == CH, "SQ must be log2(CH)");
static_assert(TT % CH == 0, "");

// Scratch.
__device__ float g_part[NCH * 6 * BB];   // zero-state per-chunk db partials
__device__ float g_ckpt[NCH * 6 * BB];   // true db at chunk entry
__device__ float g_m[CH * 6];            // m_s = Wx^s * Wu
__device__ float g_MC[36];               // Wx^CH

// Duplicated-pair weight table, staged by kP then copied to constant bank.
// Layout (u64 units):
//   rows i=0..5 at i*8: [Wx i0..i5 (pairs), Wu i (pair), pad]   (cw[7] = b2 pair)
//   rows j=0..19 at 48+j*16: [W1 j0..j11 (pairs), b1 j, W2 j, pad, pad]
#define CW_N 368
#define SW_ROWJ(j) (48 + (j) * 16)
__device__ u64 g_wdup[CW_N];
__constant__ __align__(16) u64 cw[CW_N];

// ---- f32x2 helpers (sm_100+ packed fp32 pipe) ----
__device__ __forceinline__ u64 pack2(float lo, float hi) {
    u64 r; asm("mov.b64 %0,{%1,%2};" : "=l"(r) : "f"(lo), "f"(hi)); return r;
}
__device__ __forceinline__ void unpack2(u64 v, float& lo, float& hi) {
    asm("mov.b64 {%0,%1},%2;" : "=f"(lo), "=f"(hi) : "l"(v));
}
__device__ __forceinline__ u64 fma2(u64 a, u64 b, u64 c) {
    u64 d; asm("fma.rn.f32x2 %0,%1,%2,%3;" : "=l"(d) : "l"(a), "l"(b), "l"(c)); return d;
}
__device__ __forceinline__ u64 mul2(u64 a, u64 b) {
    u64 d; asm("mul.rn.f32x2 %0,%1,%2;" : "=l"(d) : "l"(a), "l"(b)); return d;
}
__device__ __forceinline__ float tanh_(float x) {
    float y; asm("tanh.approx.f32 %0,%1;" : "=f"(y) : "f"(x)); return y;
}

// ============================================================
// Kernel P: precompute m_s = Wx^s Wu, Wx^CH, duplicated table.
// ============================================================
__global__ void __launch_bounds__(64) kP(const float* __restrict__ Wx,
                                         const float* __restrict__ Wu,
                                         const float* __restrict__ W1,
                                         const float* __restrict__ b1,
                                         const float* __restrict__ W2,
                                         const float* __restrict__ b2) {
    __shared__ float sM[36], sm[6], sP[36], st[36];
    int t = threadIdx.x;
    if (t < 36) sM[t] = Wx[t];
    if (t < 6)  sm[t] = Wu[t];
    __syncthreads();

    for (int s = 0; s < CH; s++) {
        if (t < 6) g_m[s * 6 + t] = sm[t];
        __syncthreads();
        float nv = 0.f;
        if (t < 6) {
#pragma unroll
            for (int k = 0; k < 6; k++) nv = fmaf(sM[t * 6 + k], sm[k], nv);
        }
        __syncthreads();
        if (t < 6) sm[t] = nv;
        __syncthreads();
    }

    if (t < 36) sP[t] = sM[t];
    __syncthreads();
    for (int p = 0; p < SQ; p++) {
        if (t < 36) {
            int i = t / 6, j = t % 6;
            float a = 0.f;
#pragma unroll
            for (int k = 0; k < 6; k++) a = fmaf(sP[i * 6 + k], sP[k * 6 + j], a);
            st[t] = a;
        }
        __syncthreads();
        if (t < 36) sP[t] = st[t];
        __syncthreads();
    }
    if (t < 36) g_MC[t] = sP[t];

    // ---- duplicated-pair weight table ----
    if (t < 36) {
        float w = Wx[t];
        g_wdup[(t / 6) * 8 + (t % 6)] = pack2(w, w);
    } else if (t < 42) {
        int i = t - 36;
        float w = Wu[i];
        g_wdup[i * 8 + 6] = pack2(w, w);
        if (i > 0) g_wdup[i * 8 + 7] = 0ull;
    } else if (t < 62) {
        int j = t - 42;
        for (int i = 0; i < 12; i++) {
            float w = W1[j * 12 + i];
            g_wdup[SW_ROWJ(j) + i] = pack2(w, w);
        }
        float bj = b1[j];
        g_wdup[SW_ROWJ(j) + 12] = pack2(bj, bj);
        float w2j = W2[j];
        g_wdup[SW_ROWJ(j) + 13] = pack2(w2j, w2j);
        g_wdup[SW_ROWJ(j) + 14] = 0ull;
        g_wdup[SW_ROWJ(j) + 15] = 0ull;
    } else if (t == 62) {
        float bv = b2[0];
        g_wdup[7] = pack2(bv, bv);   // b2 pair in row-0 pad slot
    }
}

// ============================================================
// Kernel A: per-chunk zero-state db partials via convolution.
// ============================================================
__global__ void __launch_bounds__(256) kA(const float* __restrict__ targets) {
    __shared__ float sm[CH * 6];
    int tid = threadIdx.x;
    for (int i = tid; i < CH * 6; i += 256) sm[i] = g_m[i];
    __syncthreads();

    int b = blockIdx.x * 256 + tid;
    int c = blockIdx.y;
    int t0 = c * CH;

    float acc[6] = {0.f, 0.f, 0.f, 0.f, 0.f, 0.f};
#pragma unroll 8
    for (int s = 0; s < CH; s++) {
        int t = t0 + s;
        float u = 0.f;
        if (t > 0) u = targets[(size_t)(t - 1) * BB + b];
        const float* mm = &sm[(CH - 1 - s) * 6];
#pragma unroll
        for (int i = 0; i < 6; i++) acc[i] = fmaf(mm[i], u, acc[i]);
    }
#pragma unroll
    for (int i = 0; i < 6; i++)
        g_part[((size_t)c * 6 + i) * BB + b] = acc[i];
}

// ============================================================
// Kernel B: scan across chunks: db_in(c+1) = Wx^CH * db_in(c) + partial(c).
// ============================================================
__global__ void __launch_bounds__(256) kB() {
    __shared__ float sM[36];
    int tid = threadIdx.x;
    if (tid < 36) sM[tid] = g_MC[tid];
    __syncthreads();

    int b = blockIdx.x * 256 + tid;
    float v[6] = {0.f, 0.f, 0.f, 0.f, 0.f, 0.f};
#pragma unroll 1
    for (int c = 0; c < NCH; c++) {
#pragma unroll
        for (int i = 0; i < 6; i++)
            g_ckpt[((size_t)c * 6 + i) * BB + b] = v[i];
        float pr[6];
#pragma unroll
        for (int i = 0; i < 6; i++)
            pr[i] = g_part[((size_t)c * 6 + i) * BB + b];
        float nv[6];
#pragma unroll
        for (int i = 0; i < 6; i++) {
            float a = pr[i];
#pragma unroll
            for (int j = 0; j < 6; j++) a = fmaf(sM[i * 6 + j], v[j], a);
            nv[i] = a;
        }
#pragma unroll
        for (int i = 0; i < 6; i++) v[i] = nv[i];
    }
}

// ============================================================
// Kernel C: fused MLP = R9 skeleton (constant-bank weights, LDCU->UR;
// per-thread state ni[12]; 4-row MLP chains) + ONE-STEP LDG PIPELINE:
// step s issues step s+1's x/u loads, consumes the previous iteration's
// registers, rotates at the bottom. Each LDG gets a full step (~900cyc)
// of latency cover. u prefetch needs no guard (rows c*CH..c*CH+CH-2 are
// always in-bounds); x prefetch guarded by s+1<CH.
// One thread = pair (b, b+HB) in f32x2 lanes, one chunk of CH steps.
// ============================================================
__global__ void __launch_bounds__(128, 4) kC(const float* __restrict__ inputs,
                                             const float* __restrict__ targets,
                                             float* __restrict__ out) {
    const int tid = threadIdx.x;
    const int c   = blockIdx.y;
    const int p   = blockIdx.x * 128 + tid;   // 0..HB-1
    const int b0  = p;
    const int b1i = p + HB;

    // ni[0..5] = db (live state), ni[6..11] = packed x of current step
    u64 ni[12];
#pragma unroll
    for (int i = 0; i < 6; i++)
        ni[i] = pack2(g_ckpt[((size_t)c * 6 + i) * BB + b0],
                      g_ckpt[((size_t)c * 6 + i) * BB + b1i]);

    const char* xp0 = (const char*)inputs + ((size_t)c * CH * BB + b0)  * 24;
    const char* xp1 = (const char*)inputs + ((size_t)c * CH * BB + b1i) * 24;
    const char* tp0 = (const char*)targets + ((size_t)(c * CH - 1) * BB + b0)  * 4;
    const char* tp1 = (const char*)targets + ((size_t)(c * CH - 1) * BB + b1i) * 4;
    char* op0 = (char*)out + ((size_t)c * CH * BB + b0)  * 4;
    char* op1 = (char*)out + ((size_t)c * CH * BB + b1i) * 4;

    const float b2v = ((const float*)cw)[14];   // low half of cw[7]

    // ---- preload step 0 ----
    float2 ca0 = ((const float2*)xp0)[0];
    float2 cb0 = ((const float2*)xp0)[1];
    float2 cc0 = ((const float2*)xp0)[2];
    float2 ca1 = ((const float2*)xp1)[0];
    float2 cb1 = ((const float2*)xp1)[1];
    float2 cc1 = ((const float2*)xp1)[2];
    xp0 += (size_t)BB * 24;
    xp1 += (size_t)BB * 24;

    float cu0 = 0.f, cu1 = 0.f;
    if (c > 0) {                      // t = c*CH; targets row t-1
        cu0 = *(const float*)tp0;
        cu1 = *(const float*)tp1;
    }
    tp0 += (size_t)BB * 4;
    tp1 += (size_t)BB * 4;

#pragma unroll 1
    for (int s = 0; s < CH; s++) {
        // ---- prefetch step s+1 (x guarded; u always in-bounds) ----
        float2 na0 = make_float2(0.f, 0.f), nb0 = na0, nc0 = na0;
        float2 na1 = na0, nb1 = na0, nc1 = na0;
        if (s + 1 < CH) {
            na0 = ((const float2*)xp0)[0];
            nb0 = ((const float2*)xp0)[1];
            nc0 = ((const float2*)xp0)[2];
            na1 = ((const float2*)xp1)[0];
            nb1 = ((const float2*)xp1)[1];
            nc1 = ((const float2*)xp1)[2];
        }
        xp0 += (size_t)BB * 24;
        xp1 += (size_t)BB * 24;
        float nu0 = *(const float*)tp0;   // row c*CH+s, always valid (<= 1022)
        float nu1 = *(const float*)tp1;
        tp0 += (size_t)BB * 4;
        tp1 += (size_t)BB * 4;

        // ---- db recurrence: ni[0..5] <- Wx*ni[0..5] + Wu*u ----
        u64 uu = pack2(cu0, cu1);
        u64 nd[6];
#pragma unroll
        for (int i = 0; i < 6; i++) {
            const u64* r = &cw[i * 8];
            u64 a = mul2(r[6], uu);
            a = fma2(r[0], ni[0], a);
            a = fma2(r[1], ni[1], a);
            a = fma2(r[2], ni[2], a);
            a = fma2(r[3], ni[3], a);
            a = fma2(r[4], ni[4], a);
            a = fma2(r[5], ni[5], a);
            nd[i] = a;
        }
#pragma unroll
        for (int i = 0; i < 6; i++) ni[i] = nd[i];
        ni[6]  = pack2(ca0.x, ca1.x);
        ni[7]  = pack2(ca0.y, ca1.y);
        ni[8]  = pack2(cb0.x, cb1.x);
        ni[9]  = pack2(cb0.y, cb1.y);
        ni[10] = pack2(cc0.x, cc1.x);
        ni[11] = pack2(cc0.y, cc1.y);

        // ---- MLP: 20 hidden rows, 4 concurrent chains per group ----
        float o0 = b2v, o1 = b2v;
#pragma unroll
        for (int jg = 0; jg < 5; jg++) {
            const int j0 = jg * 4;
            u64 a0 = cw[SW_ROWJ(j0 + 0) + 12];
            u64 a1 = cw[SW_ROWJ(j0 + 1) + 12];
            u64 a2 = cw[SW_ROWJ(j0 + 2) + 12];
            u64 a3 = cw[SW_ROWJ(j0 + 3) + 12];
#pragma unroll
            for (int k = 0; k < 12; k++) {
                a0 = fma2(cw[SW_ROWJ(j0 + 0) + k], ni[k], a0);
                a1 = fma2(cw[SW_ROWJ(j0 + 1) + k], ni[k], a1);
                a2 = fma2(cw[SW_ROWJ(j0 + 2) + k], ni[k], a2);
                a3 = fma2(cw[SW_ROWJ(j0 + 3) + k], ni[k], a3);
            }
            float lo, hi, w2;
            unpack2(a0, lo, hi);
            w2 = ((const float*)cw)[(SW_ROWJ(j0 + 0) + 13) * 2];
            o0 = fmaf(w2, tanh_(lo), o0);
            o1 = fmaf(w2, tanh_(hi), o1);
            unpack2(a1, lo, hi);
            w2 = ((const float*)cw)[(SW_ROWJ(j0 + 1) + 13) * 2];
            o0 = fmaf(w2, tanh_(lo), o0);
            o1 = fmaf(w2, tanh_(hi), o1);
            unpack2(a2, lo, hi);
            w2 = ((const float*)cw)[(SW_ROWJ(j0 + 2) + 13) * 2];
            o0 = fmaf(w2, tanh_(lo), o0);
            o1 = fmaf(w2, tanh_(hi), o1);
            unpack2(a3, lo, hi);
            w2 = ((const float*)cw)[(SW_ROWJ(j0 + 3) + 13) * 2];
            o0 = fmaf(w2, tanh_(lo), o0);
            o1 = fmaf(w2, tanh_(hi), o1);
        }

        // ---- stores ----
        *(float*)op0 = o0;
        *(float*)op1 = o1;
        op0 += (size_t)BB * 4;
        op1 += (size_t)BB * 4;

        // ---- rotate pipeline registers ----
        ca0 = na0; cb0 = nb0; cc0 = nc0;
        ca1 = na1; cb1 = nb1; cc1 = nc1;
        cu0 = nu0; cu1 = nu1;
    }
}

// ============================================================
extern "C" void kernel_launch(void* const* d_in, const int* in_sizes, int n_in,
                              void* d_out, int out_size) {
    (void)in_sizes; (void)n_in; (void)out_size;
    const float* inputs  = (const float*)d_in[0];
    const float* targets = (const float*)d_in[1];
    const float* Wx      = (const float*)d_in[2];
    const float* Wu      = (const float*)d_in[3];
    const float* W1      = (const float*)d_in[4];
    const float* b1      = (const float*)d_in[5];
    const float* W2      = (const float*)d_in[6];
    const float* b2      = (const float*)d_in[7];
    float* out = (float*)d_out;

    kP<<<1, 64>>>(Wx, Wu, W1, b1, W2, b2);

    // Stage the duplicated weight table into the constant bank (D2D memcpy node).
    void* wd = nullptr;
    cudaGetSymbolAddress(&wd, g_wdup);
    cudaMemcpyToSymbolAsync(cw, wd, CW_N * sizeof(u64), 0,
                            cudaMemcpyDeviceToDevice, 0);

    dim3 gA(BB / 256, NCH);
    kA<<<gA, 256>>>(targets);
    kB<<<BB / 256, 256>>>();
    dim3 gC(HB / 128, NCH);
    kC<<<gC, 128>>>(inputs, targets, out);
}

// round 17
// speedup vs baseline: 1.5207x; 1.1956x over previous
#include <cuda_runtime.h>

// Problem constants (fixed by the reference).
#define TT   1024
#define BB   16384
#define CH   32          // steps per chunk
#define SQ   5           // log2(CH) squarings for Wx^CH
#define NCH  (TT / CH)   // 32 chunks
#define HB   (BB / 2)    // number of adjacent pairs

typedef unsigned long long u64;

static_assert((1 << SQ) == CH, "SQ must be log2(CH)");
static_assert(TT % CH == 0, "");

// Scratch.
__device__ float g_part[NCH * 6 * BB];   // zero-state per-chunk db partials
__device__ float g_ckpt[NCH * 6 * BB];   // true db at chunk entry
__device__ float g_m[CH * 6];            // m_s = Wx^s * Wu
__device__ float g_MC[36];               // Wx^CH

// Duplicated-pair weight table, staged by kP then copied to constant bank.
// Layout (u64 units):
//   rows i=0..5 at i*8: [Wx i0..i5 (pairs), Wu i (pair), pad]   (cw[7] = b2 pair)
//   rows j=0..19 at 48+j*16: [W1 j0..j11 (pairs), b1 j, W2 j, pad, pad]
#define CW_N 368
#define SW_ROWJ(j) (48 + (j) * 16)
__device__ u64 g_wdup[CW_N];
__constant__ __align__(16) u64 cw[CW_N];

// ---- f32x2 helpers (sm_100+ packed fp32 pipe) ----
__device__ __forceinline__ u64 pack2(float lo, float hi) {
    u64 r; asm("mov.b64 %0,{%1,%2};" : "=l"(r) : "f"(lo), "f"(hi)); return r;
}
__device__ __forceinline__ void unpack2(u64 v, float& lo, float& hi) {
    asm("mov.b64 {%0,%1},%2;" : "=f"(lo), "=f"(hi) : "l"(v));
}
__device__ __forceinline__ u64 fma2(u64 a, u64 b, u64 c) {
    u64 d; asm("fma.rn.f32x2 %0,%1,%2,%3;" : "=l"(d) : "l"(a), "l"(b), "l"(c)); return d;
}
__device__ __forceinline__ u64 mul2(u64 a, u64 b) {
    u64 d; asm("mul.rn.f32x2 %0,%1,%2;" : "=l"(d) : "l"(a), "l"(b)); return d;
}
__device__ __forceinline__ float tanh_(float x) {
    float y; asm("tanh.approx.f32 %0,%1;" : "=f"(y) : "f"(x)); return y;
}

// ============================================================
// Kernel P: precompute m_s = Wx^s Wu, Wx^CH, duplicated table.
// ============================================================
__global__ void __launch_bounds__(64) kP(const float* __restrict__ Wx,
                                         const float* __restrict__ Wu,
                                         const float* __restrict__ W1,
                                         const float* __restrict__ b1,
                                         const float* __restrict__ W2,
                                         const float* __restrict__ b2) {
    __shared__ float sM[36], sm[6], sP[36], st[36];
    int t = threadIdx.x;
    if (t < 36) sM[t] = Wx[t];
    if (t < 6)  sm[t] = Wu[t];
    __syncthreads();

    for (int s = 0; s < CH; s++) {
        if (t < 6) g_m[s * 6 + t] = sm[t];
        __syncthreads();
        float nv = 0.f;
        if (t < 6) {
#pragma unroll
            for (int k = 0; k < 6; k++) nv = fmaf(sM[t * 6 + k], sm[k], nv);
        }
        __syncthreads();
        if (t < 6) sm[t] = nv;
        __syncthreads();
    }

    if (t < 36) sP[t] = sM[t];
    __syncthreads();
    for (int p = 0; p < SQ; p++) {
        if (t < 36) {
            int i = t / 6, j = t % 6;
            float a = 0.f;
#pragma unroll
            for (int k = 0; k < 6; k++) a = fmaf(sP[i * 6 + k], sP[k * 6 + j], a);
            st[t] = a;
        }
        __syncthreads();
        if (t < 36) sP[t] = st[t];
        __syncthreads();
    }
    if (t < 36) g_MC[t] = sP[t];

    // ---- duplicated-pair weight table ----
    if (t < 36) {
        float w = Wx[t];
        g_wdup[(t / 6) * 8 + (t % 6)] = pack2(w, w);
    } else if (t < 42) {
        int i = t - 36;
        float w = Wu[i];
        g_wdup[i * 8 + 6] = pack2(w, w);
        if (i > 0) g_wdup[i * 8 + 7] = 0ull;
    } else if (t < 62) {
        int j = t - 42;
        for (int i = 0; i < 12; i++) {
            float w = W1[j * 12 + i];
            g_wdup[SW_ROWJ(j) + i] = pack2(w, w);
        }
        float bj = b1[j];
        g_wdup[SW_ROWJ(j) + 12] = pack2(bj, bj);
        float w2j = W2[j];
        g_wdup[SW_ROWJ(j) + 13] = pack2(w2j, w2j);
        g_wdup[SW_ROWJ(j) + 14] = 0ull;
        g_wdup[SW_ROWJ(j) + 15] = 0ull;
    } else if (t == 62) {
        float bv = b2[0];
        g_wdup[7] = pack2(bv, bv);   // b2 pair in row-0 pad slot
    }
}

// ============================================================
// Kernel A: per-chunk zero-state db partials via convolution.
// ============================================================
__global__ void __launch_bounds__(256) kA(const float* __restrict__ targets) {
    __shared__ float sm[CH * 6];
    int tid = threadIdx.x;
    for (int i = tid; i < CH * 6; i += 256) sm[i] = g_m[i];
    __syncthreads();

    int b = blockIdx.x * 256 + tid;
    int c = blockIdx.y;
    int t0 = c * CH;

    float acc[6] = {0.f, 0.f, 0.f, 0.f, 0.f, 0.f};
#pragma unroll 8
    for (int s = 0; s < CH; s++) {
        int t = t0 + s;
        float u = 0.f;
        if (t > 0) u = targets[(size_t)(t - 1) * BB + b];
        const float* mm = &sm[(CH - 1 - s) * 6];
#pragma unroll
        for (int i = 0; i < 6; i++) acc[i] = fmaf(mm[i], u, acc[i]);
    }
#pragma unroll
    for (int i = 0; i < 6; i++)
        g_part[((size_t)c * 6 + i) * BB + b] = acc[i];
}

// ============================================================
// Kernel B: scan across chunks: db_in(c+1) = Wx^CH * db_in(c) + partial(c).
// ============================================================
__global__ void __launch_bounds__(256) kB() {
    __shared__ float sM[36];
    int tid = threadIdx.x;
    if (tid < 36) sM[tid] = g_MC[tid];
    __syncthreads();

    int b = blockIdx.x * 256 + tid;
    float v[6] = {0.f, 0.f, 0.f, 0.f, 0.f, 0.f};
#pragma unroll 1
    for (int c = 0; c < NCH; c++) {
#pragma unroll
        for (int i = 0; i < 6; i++)
            g_ckpt[((size_t)c * 6 + i) * BB + b] = v[i];
        float pr[6];
#pragma unroll
        for (int i = 0; i < 6; i++)
            pr[i] = g_part[((size_t)c * 6 + i) * BB + b];
        float nv[6];
#pragma unroll
        for (int i = 0; i < 6; i++) {
            float a = pr[i];
#pragma unroll
            for (int j = 0; j < 6; j++) a = fmaf(sM[i * 6 + j], v[j], a);
            nv[i] = a;
        }
#pragma unroll
        for (int i = 0; i < 6; i++) v[i] = nv[i];
    }
}

// ============================================================
// Kernel C: fused MLP = R16 skeleton (constant-bank weights, LDCU->UR;
// ni[12] state; 4-row MLP chains; one-step LDG pipeline) with ADJACENT
// element pairing (2p, 2p+1):
//   x  = 48 contiguous bytes -> 3x LDG.128 (prefetched as uint4)
//   u  = contiguous pair      -> 1x LDG.64 directly into the packed u64
//   db = float2 ckpt loads; out = 1x STG.64
// One pointer per stream (no lane-1 pointers).
// ============================================================
__global__ void __launch_bounds__(128, 4) kC(const float* __restrict__ inputs,
                                             const float* __restrict__ targets,
                                             float* __restrict__ out) {
    const int tid = threadIdx.x;
    const int c   = blockIdx.y;
    const int p   = blockIdx.x * 128 + tid;   // pair index 0..HB-1
    const int e0  = p * 2;                    // first of 2 adjacent elements

    // ni[0..5] = db (live state), ni[6..11] = packed x of current step
    u64 ni[12];
    {
        const char* ck = (const char*)g_ckpt + ((size_t)c * 6 * BB + e0) * 4;
#pragma unroll
        for (int i = 0; i < 6; i++) {
            float2 v = *(const float2*)(ck + (size_t)i * BB * 4);
            ni[i] = pack2(v.x, v.y);
        }
    }

    const char* xp = (const char*)inputs  + ((size_t)c * CH * BB + e0) * 24;
    const char* tp = (const char*)targets + ((size_t)(c * CH - 1) * BB + e0) * 4;
    char*       op = (char*)out           + ((size_t)c * CH * BB + e0) * 4;

    const float b2v = ((const float*)cw)[14];   // low half of cw[7]

    // ---- preload step 0 ----
    uint4 cq0 = ((const uint4*)xp)[0];
    uint4 cq1 = ((const uint4*)xp)[1];
    uint4 cq2 = ((const uint4*)xp)[2];
    xp += (size_t)BB * 24;

    u64 cu = 0ull;
    if (c > 0)                       // t = c*CH; targets row t-1
        cu = *(const u64*)tp;
    tp += (size_t)BB * 4;

#pragma unroll 1
    for (int s = 0; s < CH; s++) {
        // ---- prefetch step s+1 (x guarded; u always in-bounds) ----
        uint4 nq0 = make_uint4(0u, 0u, 0u, 0u), nq1 = nq0, nq2 = nq0;
        if (s + 1 < CH) {
            nq0 = ((const uint4*)xp)[0];
            nq1 = ((const uint4*)xp)[1];
            nq2 = ((const uint4*)xp)[2];
        }
        xp += (size_t)BB * 24;
        u64 nu = *(const u64*)tp;   // row c*CH+s, always valid (<= 1022)
        tp += (size_t)BB * 4;

        // ---- db recurrence: ni[0..5] <- Wx*ni[0..5] + Wu*u ----
        u64 nd[6];
#pragma unroll
        for (int i = 0; i < 6; i++) {
            const u64* r = &cw[i * 8];
            u64 a = mul2(r[6], cu);
            a = fma2(r[0], ni[0], a);
            a = fma2(r[1], ni[1], a);
            a = fma2(r[2], ni[2], a);
            a = fma2(r[3], ni[3], a);
            a = fma2(r[4], ni[4], a);
            a = fma2(r[5], ni[5], a);
            nd[i] = a;
        }
#pragma unroll
        for (int i = 0; i < 6; i++) ni[i] = nd[i];
        // elem0 feats = cq0.x..cq1.y, elem1 feats = cq1.z..cq2.w (as floats)
        ni[6]  = pack2(__uint_as_float(cq0.x), __uint_as_float(cq1.z));
        ni[7]  = pack2(__uint_as_float(cq0.y), __uint_as_float(cq1.w));
        ni[8]  = pack2(__uint_as_float(cq0.z), __uint_as_float(cq2.x));
        ni[9]  = pack2(__uint_as_float(cq0.w), __uint_as_float(cq2.y));
        ni[10] = pack2(__uint_as_float(cq1.x), __uint_as_float(cq2.z));
        ni[11] = pack2(__uint_as_float(cq1.y), __uint_as_float(cq2.w));

        // ---- MLP: 20 hidden rows, 4 concurrent chains per group ----
        float o0 = b2v, o1 = b2v;
#pragma unroll
        for (int jg = 0; jg < 5; jg++) {
            const int j0 = jg * 4;
            u64 a0 = cw[SW_ROWJ(j0 + 0) + 12];
            u64 a1 = cw[SW_ROWJ(j0 + 1) + 12];
            u64 a2 = cw[SW_ROWJ(j0 + 2) + 12];
            u64 a3 = cw[SW_ROWJ(j0 + 3) + 12];
#pragma unroll
            for (int k = 0; k < 12; k++) {
                a0 = fma2(cw[SW_ROWJ(j0 + 0) + k], ni[k], a0);
                a1 = fma2(cw[SW_ROWJ(j0 + 1) + k], ni[k], a1);
                a2 = fma2(cw[SW_ROWJ(j0 + 2) + k], ni[k], a2);
                a3 = fma2(cw[SW_ROWJ(j0 + 3) + k], ni[k], a3);
            }
            float lo, hi, w2;
            unpack2(a0, lo, hi);
            w2 = ((const float*)cw)[(SW_ROWJ(j0 + 0) + 13) * 2];
            o0 = fmaf(w2, tanh_(lo), o0);
            o1 = fmaf(w2, tanh_(hi), o1);
            unpack2(a1, lo, hi);
            w2 = ((const float*)cw)[(SW_ROWJ(j0 + 1) + 13) * 2];
            o0 = fmaf(w2, tanh_(lo), o0);
            o1 = fmaf(w2, tanh_(hi), o1);
            unpack2(a2, lo, hi);
            w2 = ((const float*)cw)[(SW_ROWJ(j0 + 2) + 13) * 2];
            o0 = fmaf(w2, tanh_(lo), o0);
            o1 = fmaf(w2, tanh_(hi), o1);
            unpack2(a3, lo, hi);
            w2 = ((const float*)cw)[(SW_ROWJ(j0 + 3) + 13) * 2];
            o0 = fmaf(w2, tanh_(lo), o0);
            o1 = fmaf(w2, tanh_(hi), o1);
        }

        // ---- store: adjacent pair, one STG.64 ----
        *(float2*)op = make_float2(o0, o1);
        op += (size_t)BB * 4;

        // ---- rotate pipeline registers ----
        cq0 = nq0; cq1 = nq1; cq2 = nq2;
        cu = nu;
    }
}

// ============================================================
extern "C" void kernel_launch(void* const* d_in, const int* in_sizes, int n_in,
                              void* d_out, int out_size) {
    (void)in_sizes; (void)n_in; (void)out_size;
    const float* inputs  = (const float*)d_in[0];
    const float* targets = (const float*)d_in[1];
    const float* Wx      = (const float*)d_in[2];
    const float* Wu      = (const float*)d_in[3];
    const float* W1      = (const float*)d_in[4];
    const float* b1      = (const float*)d_in[5];
    const float* W2      = (const float*)d_in[6];
    const float* b2      = (const float*)d_in[7];
    float* out = (float*)d_out;

    kP<<<1, 64>>>(Wx, Wu, W1, b1, W2, b2);

    // Stage the duplicated weight table into the constant bank (D2D memcpy node).
    void* wd = nullptr;
    cudaGetSymbolAddress(&wd, g_wdup);
    cudaMemcpyToSymbolAsync(cw, wd, CW_N * sizeof(u64), 0,
                            cudaMemcpyDeviceToDevice, 0);

    dim3 gA(BB / 256, NCH);
    kA<<<gA, 256>>>(targets);
    kB<<<BB / 256, 256>>>();
    dim3 gC(HB / 128, NCH);
    kC<<<gC, 128>>>(inputs, targets, out);
}